// round 6
// baseline (speedup 1.0000x reference)
#include <cuda_runtime.h>
#include <math.h>

#define DIM   1024
#define NC    8
#define NPER  4096
#define QDIM  128
#define TOPK  128

// Scratch (no allocations allowed -> __device__ globals)
__device__ float g_w[NC][DIM];                   // q_w^T @ qk per cluster
__device__ float g_b0[NC];                       // q_b . qk
__device__ unsigned long long g_keys[NC][NPER];  // (desc-map(score)<<32)|idx
__device__ int   g_topidx[NC][TOPK];             // sorted top-k indices
__device__ float g_gvec[NC][DIM];                // sum_n e^{s_n} feats[n]
__device__ float g_Z[NC];                        // sum_n e^{s_n}

// ---------------------------------------------------------------------------
// No-op kernel: aligns ncu's fixed "-s 5 -c 1" capture window onto
// fused_pass_kernel (harness emits 2 launches before ours; capture = 4th of
// ours). Two of these + prep = 3 launches, so fused_pass is captured.
// ---------------------------------------------------------------------------
__global__ void noop_kernel() {}

// ---------------------------------------------------------------------------
// Kernel A: per-cluster qk = key@q_w^T + q_b ; w = q_w^T @ qk ; b0 = q_b.qk
// Also zeroes g_gvec / g_Z. grid = NC, block = 1024.
// ---------------------------------------------------------------------------
__global__ __launch_bounds__(1024) void prep_kernel(const float* __restrict__ key_feats,
                                                    const float* __restrict__ q_w,
                                                    const float* __restrict__ q_b) {
    __shared__ __align__(16) float s_qk[QDIM];
    __shared__ float red[4];
    int c = blockIdx.x;
    int t = threadIdx.x;
    int warp = t >> 5, lane = t & 31;

    g_gvec[c][t] = 0.f;          // t covers all DIM=1024
    if (t == 0) g_Z[c] = 0.f;

    // qk[q] via warp-per-row dots (32 warps x 4 rounds = 128 rows)
    const float4* kr = (const float4*)(key_feats + (size_t)c * DIM);
    #pragma unroll
    for (int rr = 0; rr < 4; rr++) {
        int q = warp + rr * 32;
        const float4* qr = (const float4*)(q_w + (size_t)q * DIM);
        float a = 0.f;
        #pragma unroll
        for (int k = 0; k < 8; k++) {
            float4 x = qr[lane + k * 32], y = kr[lane + k * 32];
            a += x.x * y.x + x.y * y.y + x.z * y.z + x.w * y.w;
        }
        #pragma unroll
        for (int o = 16; o > 0; o >>= 1)
            a += __shfl_xor_sync(0xffffffffu, a, o);
        if (lane == 0) s_qk[q] = a + q_b[q];
    }
    __syncthreads();

    // w[t] = sum_q qk[q] * q_w[q][t]  (coalesced across t)
    float wacc = 0.f;
    #pragma unroll 16
    for (int q = 0; q < QDIM; q++)
        wacc += s_qk[q] * q_w[(size_t)q * DIM + t];
    g_w[c][t] = wacc;

    // b0 = qk . q_b (threads 0..127)
    if (t < QDIM) {
        float p = s_qk[t] * q_b[t];
        #pragma unroll
        for (int o = 16; o > 0; o >>= 1)
            p += __shfl_xor_sync(0xffffffffu, p, o);
        if (lane == 0) red[warp] = p;
    }
    __syncthreads();
    if (t == 0) g_b0[c] = red[0] + red[1] + red[2] + red[3];
}

// ---------------------------------------------------------------------------
// Kernel B (fused single pass over feats, register-resident rows):
// warp owns a row: loads 8 float4/lane, dot vs w (smem), s -> key (g_keys),
// e = exp(s), acc += e*row (registers). Block-combine + global atomics.
// grid = NC*64 (64 rows/block), block = 256 (8 warps x 8 rows each)
// ---------------------------------------------------------------------------
__global__ __launch_bounds__(256) void fused_pass_kernel(const float* __restrict__ feats) {
    __shared__ __align__(16) float sw[DIM];
    __shared__ __align__(16) float sacc[DIM];
    __shared__ float zsh;

    int bid = blockIdx.x;
    int c = bid >> 6;
    int base = (bid & 63) * 64;
    int t = threadIdx.x, warp = t >> 5, lane = t & 31;

    ((float4*)sw)[t] = ((const float4*)(g_w[c]))[t];
    ((float4*)sacc)[t] = make_float4(0.f, 0.f, 0.f, 0.f);
    if (t == 0) zsh = 0.f;
    float b0 = g_b0[c];
    __syncthreads();

    const float4* fb =
        (const float4*)(feats + ((size_t)c * NPER + base + (size_t)warp * 8) * DIM);

    float4 acc[8];
    #pragma unroll
    for (int k = 0; k < 8; k++) acc[k] = make_float4(0.f, 0.f, 0.f, 0.f);
    float zw = 0.f;

    for (int r = 0; r < 8; r++) {
        float4 f[8];
        #pragma unroll
        for (int k = 0; k < 8; k++)
            f[k] = fb[(size_t)r * 256 + lane + k * 32];

        float d = 0.f;
        #pragma unroll
        for (int k = 0; k < 8; k++) {
            float4 w4 = ((const float4*)sw)[lane + k * 32];
            d += f[k].x * w4.x + f[k].y * w4.y + f[k].z * w4.z + f[k].w * w4.w;
        }
        #pragma unroll
        for (int o = 16; o > 0; o >>= 1)
            d += __shfl_xor_sync(0xffffffffu, d, o);

        float s = (d + b0) * 0.08838834764831845f;  // 1/sqrt(128)
        float e = expf(s);                           // |s| small: safe
        zw += e;

        if (lane == 0) {
            int n = base + warp * 8 + r;
            unsigned u = __float_as_uint(s);
            u = (u & 0x80000000u) ? ~u : (u | 0x80000000u);  // ascending map
            unsigned dm = ~u;                                // descending map
            g_keys[c][n] = ((unsigned long long)dm << 32) | (unsigned)n;
        }

        #pragma unroll
        for (int k = 0; k < 8; k++) {
            acc[k].x += e * f[k].x; acc[k].y += e * f[k].y;
            acc[k].z += e * f[k].z; acc[k].w += e * f[k].w;
        }
    }

    // cross-warp combine (serialized rounds)
    for (int wi = 0; wi < 8; wi++) {
        if (warp == wi) {
            #pragma unroll
            for (int k = 0; k < 8; k++) {
                float4* p = &((float4*)sacc)[lane + k * 32];
                float4 v = *p;
                v.x += acc[k].x; v.y += acc[k].y;
                v.z += acc[k].z; v.w += acc[k].w;
                *p = v;
            }
            if (lane == 0) zsh += zw;
        }
        __syncthreads();
    }

    float4 v = ((float4*)sacc)[t];
    float* gp = g_gvec[c] + t * 4;
    atomicAdd(gp + 0, v.x);
    atomicAdd(gp + 1, v.y);
    atomicAdd(gp + 2, v.z);
    atomicAdd(gp + 3, v.w);
    if (t == 0) atomicAdd(&g_Z[c], zsh);
}

// ---------------------------------------------------------------------------
// Kernel C: exact top-128 via 8-level MSD radix select on 64-bit keys
// (warp-aggregated histograms + warp-shuffle scan), then bitonic sort of
// the 128 winners. grid = NC, block = 1024.
// ---------------------------------------------------------------------------
__global__ __launch_bounds__(1024) void topk_kernel() {
    __shared__ unsigned hist[256];
    __shared__ unsigned wsum[8];
    __shared__ unsigned long long s_prefix;
    __shared__ unsigned s_remaining;
    __shared__ unsigned long long winners[TOPK];
    __shared__ unsigned wcnt;

    int c = blockIdx.x;
    int t = threadIdx.x;
    int warp = t >> 5, lane = t & 31;

    unsigned long long key[4];
    #pragma unroll
    for (int i = 0; i < 4; i++) key[i] = g_keys[c][t + i * 1024];

    unsigned long long prefix = 0ull, mask = 0ull;
    unsigned remaining = TOPK;

    for (int level = 0; level < 8; level++) {
        int shift = 56 - 8 * level;
        if (t < 256) hist[t] = 0u;
        __syncthreads();

        // warp-aggregated histogram (clustered digits -> few atomics)
        #pragma unroll
        for (int i = 0; i < 4; i++) {
            bool active = ((key[i] & mask) == prefix);
            unsigned digit = active
                ? (unsigned)((key[i] >> shift) & 255u)
                : (256u + (unsigned)lane);          // unique -> self group
            unsigned grp = __match_any_sync(0xffffffffu, digit);
            int leader = __ffs(grp) - 1;
            if (active && lane == leader)
                atomicAdd(&hist[digit], (unsigned)__popc(grp));
        }
        __syncthreads();

        // inclusive scan of hist[256] via warps 0..7
        unsigned own = 0u, v = 0u;
        if (t < 256) {
            own = hist[t];
            v = own;
            #pragma unroll
            for (int o = 1; o < 32; o <<= 1) {
                unsigned u = __shfl_up_sync(0xffffffffu, v, o);
                if (lane >= o) v += u;
            }
            if (lane == 31) wsum[warp] = v;
        }
        __syncthreads();
        if (t == 0) {
            unsigned srun = 0u;
            #pragma unroll
            for (int i = 0; i < 8; i++) { unsigned x = wsum[i]; wsum[i] = srun; srun += x; }
        }
        __syncthreads();
        if (t < 256) {
            unsigned incl = v + wsum[warp];
            unsigned excl = incl - own;
            if (own > 0u && excl < remaining && incl >= remaining) {
                s_prefix = prefix | ((unsigned long long)(unsigned)t << shift);
                s_remaining = remaining - excl;
            }
        }
        __syncthreads();
        prefix = s_prefix;
        remaining = s_remaining;
        mask |= (0xffull << shift);
    }

    // prefix == exact 128th-smallest key; winners are keys <= prefix
    if (t == 0) wcnt = 0u;
    __syncthreads();
    #pragma unroll
    for (int i = 0; i < 4; i++) {
        if (key[i] <= prefix) {
            unsigned p = atomicAdd(&wcnt, 1u);
            winners[p] = key[i];
        }
    }
    __syncthreads();

    // bitonic sort 128 winners ascending (desc score, asc idx)
    for (unsigned k = 2; k <= TOPK; k <<= 1) {
        for (unsigned j = k >> 1; j > 0; j >>= 1) {
            if (t < TOPK) {
                unsigned i = (unsigned)t, ixj = i ^ j;
                if (ixj > i) {
                    unsigned long long a = winners[i], b = winners[ixj];
                    bool up = ((i & k) == 0);
                    if ((a > b) == up) { winners[i] = b; winners[ixj] = a; }
                }
            }
            __syncthreads();
        }
    }

    if (t < TOPK)
        g_topidx[c][t] = (int)(unsigned)(winners[t] & 0xffffffffu);
}

// ---------------------------------------------------------------------------
// Kernel D (merged gather + fusion), block = 256:
//   blocks [0, 1024):      gather row b: out[row] = feats[c][topidx[c][k]]
//   blocks [1024, 2048):   fusion: 8 outputs per block (warp-per-output)
// ---------------------------------------------------------------------------
__global__ __launch_bounds__(256) void gather_fusion_kernel(
        const float* __restrict__ feats,
        const float* __restrict__ v_w,
        const float* __restrict__ v_b,
        float* __restrict__ out) {
    __shared__ __align__(16) float sg[DIM];
    int t = threadIdx.x;

    if (blockIdx.x < 1024) {
        // ---- gather ----
        int row = blockIdx.x;
        int c = row >> 7, k = row & 127;
        int src = g_topidx[c][k];
        const float4* s =
            (const float4*)(feats + ((size_t)c * NPER + src) * DIM);
        float4* dst = (float4*)(out + (size_t)row * DIM);
        dst[t] = s[t];
        return;
    }

    // ---- fusion ----
    int bid = blockIdx.x - 1024;   // 0..1023
    int c = bid >> 7;
    int o0 = (bid & 127) * 8;

    float invZ = 1.f / g_Z[c];
    float4 gv = ((const float4*)(g_gvec[c]))[t];
    gv.x *= invZ; gv.y *= invZ; gv.z *= invZ; gv.w *= invZ;
    ((float4*)sg)[t] = gv;
    __syncthreads();

    int warp = t >> 5, lane = t & 31;
    int o = o0 + warp;
    const float4* vr = (const float4*)(v_w + (size_t)o * DIM);
    const float4* gr = (const float4*)sg;
    float acc = 0.f;
    #pragma unroll
    for (int i = 0; i < 8; i++) {
        int idx = lane + i * 32;
        float4 a = vr[idx], b = gr[idx];
        acc += a.x * b.x + a.y * b.y + a.z * b.z + a.w * b.w;
    }
    #pragma unroll
    for (int ofs = 16; ofs > 0; ofs >>= 1)
        acc += __shfl_xor_sync(0xffffffffu, acc, ofs);
    if (lane == 0)
        out[(size_t)1024 * 1024 + (size_t)c * DIM + o] = acc + v_b[o];
}

// ---------------------------------------------------------------------------
extern "C" void kernel_launch(void* const* d_in, const int* in_sizes, int n_in,
                              void* d_out, int out_size) {
    const float* feats     = (const float*)d_in[0];  // [8,4096,1024]
    const float* key_feats = (const float*)d_in[1];  // [8,1,1024]
    const float* q_w       = (const float*)d_in[2];  // [128,1024]
    const float* q_b       = (const float*)d_in[3];  // [128]
    const float* v_w       = (const float*)d_in[4];  // [1024,1024]
    const float* v_b       = (const float*)d_in[5];  // [1024]
    float* out = (float*)d_out;  // selected [1024,1024] then fus [8,1024]

    noop_kernel<<<1, 32>>>();   // ncu capture alignment (see comment above)
    noop_kernel<<<1, 32>>>();
    prep_kernel<<<NC, 1024>>>(key_feats, q_w, q_b);
    fused_pass_kernel<<<NC * 64, 256>>>(feats);   // <- 4th launch: profiled
    topk_kernel<<<NC, 1024>>>();
    gather_fusion_kernel<<<2048, 256>>>(feats, v_w, v_b, out);
}

// round 7
// speedup vs baseline: 1.2909x; 1.2909x over previous
#include <cuda_runtime.h>
#include <math.h>

#define DIM   1024
#define NC    8
#define NPER  4096
#define QDIM  128
#define TOPK  128

// Scratch (no allocations allowed -> __device__ globals)
__device__ float g_w[NC][DIM];                   // q_w^T @ qk per cluster
__device__ float g_b0[NC];                       // q_b . qk
__device__ unsigned long long g_keys[NC][NPER];  // (desc-map(score)<<32)|idx
__device__ int   g_topidx[NC][TOPK];             // sorted top-k indices
__device__ float g_gvec[NC][DIM];                // sum_n e^{s_n} feats[n]
__device__ float g_Z[NC];                        // sum_n e^{s_n}

// ---------------------------------------------------------------------------
// No-op kernel: aligns ncu's fixed capture slot (my 4th launch) onto
// topk_kernel: [noop, prep, fused, topk, gather_fusion].
// ---------------------------------------------------------------------------
__global__ void noop_kernel() {}

// ---------------------------------------------------------------------------
// Kernel A: per-cluster qk = key@q_w^T + q_b ; w = q_w^T @ qk ; b0 = q_b.qk
// Also zeroes g_gvec / g_Z. grid = NC, block = 1024.
// ---------------------------------------------------------------------------
__global__ __launch_bounds__(1024) void prep_kernel(const float* __restrict__ key_feats,
                                                    const float* __restrict__ q_w,
                                                    const float* __restrict__ q_b) {
    __shared__ __align__(16) float s_qk[QDIM];
    __shared__ float red[4];
    int c = blockIdx.x;
    int t = threadIdx.x;
    int warp = t >> 5, lane = t & 31;

    g_gvec[c][t] = 0.f;          // t covers all DIM=1024
    if (t == 0) g_Z[c] = 0.f;

    // qk[q] via warp-per-row dots (32 warps x 4 rounds = 128 rows)
    const float4* kr = (const float4*)(key_feats + (size_t)c * DIM);
    #pragma unroll
    for (int rr = 0; rr < 4; rr++) {
        int q = warp + rr * 32;
        const float4* qr = (const float4*)(q_w + (size_t)q * DIM);
        float a = 0.f;
        #pragma unroll
        for (int k = 0; k < 8; k++) {
            float4 x = qr[lane + k * 32], y = kr[lane + k * 32];
            a += x.x * y.x + x.y * y.y + x.z * y.z + x.w * y.w;
        }
        #pragma unroll
        for (int o = 16; o > 0; o >>= 1)
            a += __shfl_xor_sync(0xffffffffu, a, o);
        if (lane == 0) s_qk[q] = a + q_b[q];
    }
    __syncthreads();

    // w[t] = sum_q qk[q] * q_w[q][t]  (coalesced across t)
    float wacc = 0.f;
    #pragma unroll 16
    for (int q = 0; q < QDIM; q++)
        wacc += s_qk[q] * q_w[(size_t)q * DIM + t];
    g_w[c][t] = wacc;

    // b0 = qk . q_b (threads 0..127)
    if (t < QDIM) {
        float p = s_qk[t] * q_b[t];
        #pragma unroll
        for (int o = 16; o > 0; o >>= 1)
            p += __shfl_xor_sync(0xffffffffu, p, o);
        if (lane == 0) red[warp] = p;
    }
    __syncthreads();
    if (t == 0) g_b0[c] = red[0] + red[1] + red[2] + red[3];
}

// ---------------------------------------------------------------------------
// Kernel B (fused single pass over feats, register-resident rows):
// UNCHANGED from R6 (measured 31.9us). warp owns a row: 8 float4/lane, dot
// vs w (smem), s -> key (g_keys), e = exp(s), acc += e*row (registers).
// grid = NC*64, block = 256.
// ---------------------------------------------------------------------------
__global__ __launch_bounds__(256) void fused_pass_kernel(const float* __restrict__ feats) {
    __shared__ __align__(16) float sw[DIM];
    __shared__ __align__(16) float sacc[DIM];
    __shared__ float zsh;

    int bid = blockIdx.x;
    int c = bid >> 6;
    int base = (bid & 63) * 64;
    int t = threadIdx.x, warp = t >> 5, lane = t & 31;

    ((float4*)sw)[t] = ((const float4*)(g_w[c]))[t];
    ((float4*)sacc)[t] = make_float4(0.f, 0.f, 0.f, 0.f);
    if (t == 0) zsh = 0.f;
    float b0 = g_b0[c];
    __syncthreads();

    const float4* fb =
        (const float4*)(feats + ((size_t)c * NPER + base + (size_t)warp * 8) * DIM);

    float4 acc[8];
    #pragma unroll
    for (int k = 0; k < 8; k++) acc[k] = make_float4(0.f, 0.f, 0.f, 0.f);
    float zw = 0.f;

    for (int r = 0; r < 8; r++) {
        float4 f[8];
        #pragma unroll
        for (int k = 0; k < 8; k++)
            f[k] = fb[(size_t)r * 256 + lane + k * 32];

        float d = 0.f;
        #pragma unroll
        for (int k = 0; k < 8; k++) {
            float4 w4 = ((const float4*)sw)[lane + k * 32];
            d += f[k].x * w4.x + f[k].y * w4.y + f[k].z * w4.z + f[k].w * w4.w;
        }
        #pragma unroll
        for (int o = 16; o > 0; o >>= 1)
            d += __shfl_xor_sync(0xffffffffu, d, o);

        float s = (d + b0) * 0.08838834764831845f;  // 1/sqrt(128)
        float e = expf(s);                           // |s| small: safe
        zw += e;

        if (lane == 0) {
            int n = base + warp * 8 + r;
            unsigned u = __float_as_uint(s);
            u = (u & 0x80000000u) ? ~u : (u | 0x80000000u);  // ascending map
            unsigned dm = ~u;                                // descending map
            g_keys[c][n] = ((unsigned long long)dm << 32) | (unsigned)n;
        }

        #pragma unroll
        for (int k = 0; k < 8; k++) {
            acc[k].x += e * f[k].x; acc[k].y += e * f[k].y;
            acc[k].z += e * f[k].z; acc[k].w += e * f[k].w;
        }
    }

    // cross-warp combine (serialized rounds)
    for (int wi = 0; wi < 8; wi++) {
        if (warp == wi) {
            #pragma unroll
            for (int k = 0; k < 8; k++) {
                float4* p = &((float4*)sacc)[lane + k * 32];
                float4 v = *p;
                v.x += acc[k].x; v.y += acc[k].y;
                v.z += acc[k].z; v.w += acc[k].w;
                *p = v;
            }
            if (lane == 0) zsh += zw;
        }
        __syncthreads();
    }

    float4 v = ((float4*)sacc)[t];
    float* gp = g_gvec[c] + t * 4;
    atomicAdd(gp + 0, v.x);
    atomicAdd(gp + 1, v.y);
    atomicAdd(gp + 2, v.z);
    atomicAdd(gp + 3, v.w);
    if (t == 0) atomicAdd(&g_Z[c], zsh);
}

// ---------------------------------------------------------------------------
// Kernel C (rewritten): exact top-128.
// 4-level (8-bit) MSD radix select on the HIGH 32 bits (desc-mapped score).
// Then collect all keys whose score-dword <= threshold (>=128, ties incl.,
// buffer 512), and emit via rank-by-counting over candidates: candidate
// ranks equal global ranks because every non-candidate key is larger.
// grid = NC, block = 1024.
// ---------------------------------------------------------------------------
__global__ __launch_bounds__(1024) void topk_kernel() {
    __shared__ unsigned hist[256];
    __shared__ unsigned wsum[8];
    __shared__ unsigned s_prefix;
    __shared__ unsigned s_remaining;
    __shared__ unsigned long long cand[512];
    __shared__ unsigned ccnt;

    int c = blockIdx.x;
    int t = threadIdx.x;
    int warp = t >> 5, lane = t & 31;

    unsigned long long key[4];
    unsigned d32[4];
    #pragma unroll
    for (int i = 0; i < 4; i++) {
        key[i] = g_keys[c][t + i * 1024];
        d32[i] = (unsigned)(key[i] >> 32);
    }

    unsigned prefix = 0u, mask = 0u;
    unsigned remaining = TOPK;

    #pragma unroll
    for (int level = 0; level < 4; level++) {
        int shift = 24 - 8 * level;
        if (t < 256) hist[t] = 0u;
        __syncthreads();

        // warp-aggregated histogram (clustered digits -> few atomics)
        #pragma unroll
        for (int i = 0; i < 4; i++) {
            bool active = ((d32[i] & mask) == prefix);
            unsigned digit = active
                ? ((d32[i] >> shift) & 255u)
                : (256u + (unsigned)lane);          // unique -> no group
            unsigned grp = __match_any_sync(0xffffffffu, digit);
            int leader = __ffs(grp) - 1;
            if (active && lane == leader)
                atomicAdd(&hist[digit], (unsigned)__popc(grp));
        }
        __syncthreads();

        // inclusive scan of hist[256] via warp shuffles + 8-way combine
        unsigned own = 0u, v = 0u;
        if (t < 256) {
            own = hist[t];
            v = own;
            #pragma unroll
            for (int o = 1; o < 32; o <<= 1) {
                unsigned u = __shfl_up_sync(0xffffffffu, v, o);
                if (lane >= o) v += u;
            }
            if (lane == 31) wsum[warp] = v;
        }
        __syncthreads();
        if (t == 0) {
            unsigned srun = 0u;
            #pragma unroll
            for (int i = 0; i < 8; i++) { unsigned x = wsum[i]; wsum[i] = srun; srun += x; }
        }
        __syncthreads();
        if (t < 256) {
            unsigned incl = v + wsum[warp];
            unsigned excl = incl - own;
            if (own > 0u && excl < remaining && incl >= remaining) {
                s_prefix = prefix | ((unsigned)t << shift);
                s_remaining = remaining - excl;
            }
        }
        __syncthreads();
        prefix = s_prefix;
        remaining = s_remaining;
        mask |= (0xffu << shift);
    }

    // prefix = exact score-dword of the 128th-smallest key.
    // Candidates: all keys with score-dword <= prefix (count in [128, 128+ties)).
    if (t == 0) ccnt = 0u;
    __syncthreads();
    #pragma unroll
    for (int i = 0; i < 4; i++) {
        if (d32[i] <= prefix) {
            unsigned p = atomicAdd(&ccnt, 1u);
            if (p < 512u) cand[p] = key[i];
        }
    }
    __syncthreads();

    // rank-by-counting among candidates (== global rank); emit rank < 128
    unsigned cnt = ccnt < 512u ? ccnt : 512u;
    if (t < cnt) {
        unsigned long long mine = cand[t];
        unsigned rank = 0u;
        for (unsigned j = 0; j < cnt; j++)
            rank += (cand[j] < mine) ? 1u : 0u;
        if (rank < TOPK)
            g_topidx[c][rank] = (int)(unsigned)(mine & 0xffffffffu);
    }
}

// ---------------------------------------------------------------------------
// Kernel D (merged gather + fusion), block = 256:
//   blocks [0, 1024):      gather row b: out[row] = feats[c][topidx[c][k]]
//   blocks [1024, 2048):   fusion: 8 outputs per block (warp-per-output)
// ---------------------------------------------------------------------------
__global__ __launch_bounds__(256) void gather_fusion_kernel(
        const float* __restrict__ feats,
        const float* __restrict__ v_w,
        const float* __restrict__ v_b,
        float* __restrict__ out) {
    __shared__ __align__(16) float sg[DIM];
    int t = threadIdx.x;

    if (blockIdx.x < 1024) {
        // ---- gather ----
        int row = blockIdx.x;
        int c = row >> 7, k = row & 127;
        int src = g_topidx[c][k];
        const float4* s =
            (const float4*)(feats + ((size_t)c * NPER + src) * DIM);
        float4* dst = (float4*)(out + (size_t)row * DIM);
        dst[t] = s[t];
        return;
    }

    // ---- fusion ----
    int bid = blockIdx.x - 1024;   // 0..1023
    int c = bid >> 7;
    int o0 = (bid & 127) * 8;

    float invZ = 1.f / g_Z[c];
    float4 gv = ((const float4*)(g_gvec[c]))[t];
    gv.x *= invZ; gv.y *= invZ; gv.z *= invZ; gv.w *= invZ;
    ((float4*)sg)[t] = gv;
    __syncthreads();

    int warp = t >> 5, lane = t & 31;
    int o = o0 + warp;
    const float4* vr = (const float4*)(v_w + (size_t)o * DIM);
    const float4* gr = (const float4*)sg;
    float acc = 0.f;
    #pragma unroll
    for (int i = 0; i < 8; i++) {
        int idx = lane + i * 32;
        float4 a = vr[idx], b = gr[idx];
        acc += a.x * b.x + a.y * b.y + a.z * b.z + a.w * b.w;
    }
    #pragma unroll
    for (int ofs = 16; ofs > 0; ofs >>= 1)
        acc += __shfl_xor_sync(0xffffffffu, acc, ofs);
    if (lane == 0)
        out[(size_t)1024 * 1024 + (size_t)c * DIM + o] = acc + v_b[o];
}

// ---------------------------------------------------------------------------
extern "C" void kernel_launch(void* const* d_in, const int* in_sizes, int n_in,
                              void* d_out, int out_size) {
    const float* feats     = (const float*)d_in[0];  // [8,4096,1024]
    const float* key_feats = (const float*)d_in[1];  // [8,1,1024]
    const float* q_w       = (const float*)d_in[2];  // [128,1024]
    const float* q_b       = (const float*)d_in[3];  // [128]
    const float* v_w       = (const float*)d_in[4];  // [1024,1024]
    const float* v_b       = (const float*)d_in[5];  // [1024]
    float* out = (float*)d_out;  // selected [1024,1024] then fus [8,1024]

    noop_kernel<<<1, 32>>>();   // capture alignment: topk is 4th launch
    prep_kernel<<<NC, 1024>>>(key_feats, q_w, q_b);
    fused_pass_kernel<<<NC * 64, 256>>>(feats);
    topk_kernel<<<NC, 1024>>>();               // <- profiled this round
    gather_fusion_kernel<<<2048, 256>>>(feats, v_w, v_b, out);
}

// round 8
// speedup vs baseline: 1.3302x; 1.0304x over previous
#include <cuda_runtime.h>
#include <math.h>

#define DIM   1024
#define NC    8
#define NPER  4096
#define QDIM  128
#define TOPK  128

// Scratch (no allocations allowed -> __device__ globals)
__device__ float g_w[NC][DIM];                   // q_w^T @ qk per cluster
__device__ float g_b0[NC];                       // q_b . qk
__device__ unsigned long long g_keys[NC][NPER];  // (desc-map(score)<<32)|idx
__device__ int   g_topidx[NC][TOPK];             // sorted top-k indices
__device__ float g_gvec[NC][DIM];                // sum_n e^{s_n} feats[n]
__device__ float g_Z[NC];                        // sum_n e^{s_n}

// ---------------------------------------------------------------------------
// No-op kernel: keeps topk_kernel in ncu's fixed capture slot (4th launch):
// [noop, prep, fused, topk, gather_fusion].
// ---------------------------------------------------------------------------
__global__ void noop_kernel() {}

// ---------------------------------------------------------------------------
// Kernel A: per-cluster qk = key@q_w^T + q_b ; w = q_w^T @ qk ; b0 = q_b.qk
// Also zeroes g_gvec / g_Z. grid = NC, block = 1024. UNCHANGED.
// ---------------------------------------------------------------------------
__global__ __launch_bounds__(1024) void prep_kernel(const float* __restrict__ key_feats,
                                                    const float* __restrict__ q_w,
                                                    const float* __restrict__ q_b) {
    __shared__ __align__(16) float s_qk[QDIM];
    __shared__ float red[4];
    int c = blockIdx.x;
    int t = threadIdx.x;
    int warp = t >> 5, lane = t & 31;

    g_gvec[c][t] = 0.f;          // t covers all DIM=1024
    if (t == 0) g_Z[c] = 0.f;

    const float4* kr = (const float4*)(key_feats + (size_t)c * DIM);
    #pragma unroll
    for (int rr = 0; rr < 4; rr++) {
        int q = warp + rr * 32;
        const float4* qr = (const float4*)(q_w + (size_t)q * DIM);
        float a = 0.f;
        #pragma unroll
        for (int k = 0; k < 8; k++) {
            float4 x = qr[lane + k * 32], y = kr[lane + k * 32];
            a += x.x * y.x + x.y * y.y + x.z * y.z + x.w * y.w;
        }
        #pragma unroll
        for (int o = 16; o > 0; o >>= 1)
            a += __shfl_xor_sync(0xffffffffu, a, o);
        if (lane == 0) s_qk[q] = a + q_b[q];
    }
    __syncthreads();

    float wacc = 0.f;
    #pragma unroll 16
    for (int q = 0; q < QDIM; q++)
        wacc += s_qk[q] * q_w[(size_t)q * DIM + t];
    g_w[c][t] = wacc;

    if (t < QDIM) {
        float p = s_qk[t] * q_b[t];
        #pragma unroll
        for (int o = 16; o > 0; o >>= 1)
            p += __shfl_xor_sync(0xffffffffu, p, o);
        if (lane == 0) red[warp] = p;
    }
    __syncthreads();
    if (t == 0) g_b0[c] = red[0] + red[1] + red[2] + red[3];
}

// ---------------------------------------------------------------------------
// Kernel B (fused single pass over feats). UNCHANGED (measured 31.9us).
// ---------------------------------------------------------------------------
__global__ __launch_bounds__(256) void fused_pass_kernel(const float* __restrict__ feats) {
    __shared__ __align__(16) float sw[DIM];
    __shared__ __align__(16) float sacc[DIM];
    __shared__ float zsh;

    int bid = blockIdx.x;
    int c = bid >> 6;
    int base = (bid & 63) * 64;
    int t = threadIdx.x, warp = t >> 5, lane = t & 31;

    ((float4*)sw)[t] = ((const float4*)(g_w[c]))[t];
    ((float4*)sacc)[t] = make_float4(0.f, 0.f, 0.f, 0.f);
    if (t == 0) zsh = 0.f;
    float b0 = g_b0[c];
    __syncthreads();

    const float4* fb =
        (const float4*)(feats + ((size_t)c * NPER + base + (size_t)warp * 8) * DIM);

    float4 acc[8];
    #pragma unroll
    for (int k = 0; k < 8; k++) acc[k] = make_float4(0.f, 0.f, 0.f, 0.f);
    float zw = 0.f;

    for (int r = 0; r < 8; r++) {
        float4 f[8];
        #pragma unroll
        for (int k = 0; k < 8; k++)
            f[k] = fb[(size_t)r * 256 + lane + k * 32];

        float d = 0.f;
        #pragma unroll
        for (int k = 0; k < 8; k++) {
            float4 w4 = ((const float4*)sw)[lane + k * 32];
            d += f[k].x * w4.x + f[k].y * w4.y + f[k].z * w4.z + f[k].w * w4.w;
        }
        #pragma unroll
        for (int o = 16; o > 0; o >>= 1)
            d += __shfl_xor_sync(0xffffffffu, d, o);

        float s = (d + b0) * 0.08838834764831845f;  // 1/sqrt(128)
        float e = expf(s);                           // |s| small: safe
        zw += e;

        if (lane == 0) {
            int n = base + warp * 8 + r;
            unsigned u = __float_as_uint(s);
            u = (u & 0x80000000u) ? ~u : (u | 0x80000000u);  // ascending map
            unsigned dm = ~u;                                // descending map
            g_keys[c][n] = ((unsigned long long)dm << 32) | (unsigned)n;
        }

        #pragma unroll
        for (int k = 0; k < 8; k++) {
            acc[k].x += e * f[k].x; acc[k].y += e * f[k].y;
            acc[k].z += e * f[k].z; acc[k].w += e * f[k].w;
        }
    }

    for (int wi = 0; wi < 8; wi++) {
        if (warp == wi) {
            #pragma unroll
            for (int k = 0; k < 8; k++) {
                float4* p = &((float4*)sacc)[lane + k * 32];
                float4 v = *p;
                v.x += acc[k].x; v.y += acc[k].y;
                v.z += acc[k].z; v.w += acc[k].w;
                *p = v;
            }
            if (lane == 0) zsh += zw;
        }
        __syncthreads();
    }

    float4 v = ((float4*)sacc)[t];
    float* gp = g_gvec[c] + t * 4;
    atomicAdd(gp + 0, v.x);
    atomicAdd(gp + 1, v.y);
    atomicAdd(gp + 2, v.z);
    atomicAdd(gp + 3, v.w);
    if (t == 0) atomicAdd(&g_Z[c], zsh);
}

// ---------------------------------------------------------------------------
// Kernel C (atomic-free): exact top-128.
// Phase 1: bitwise kth-smallest search on the 32-bit score-dword, 2 bits per
//          iteration (16 iters), counting via ballot+popc. Zero atomics.
// Phase 2: ballot-scan compaction of candidates (d32 <= pivot) into shared.
// Phase 3: rank-by-counting emit (candidate rank == global rank).
// grid = NC, block = 1024.
// ---------------------------------------------------------------------------
__global__ __launch_bounds__(1024) void topk_kernel() {
    __shared__ unsigned shc[32][4];       // per-warp counts / scan scratch
    __shared__ unsigned red4[4];
    __shared__ unsigned s_P, s_r, s_total;
    __shared__ unsigned long long cand[512];

    int c = blockIdx.x;
    int t = threadIdx.x;
    int warp = t >> 5, lane = t & 31;

    unsigned long long key[4];
    unsigned d32[4];
    #pragma unroll
    for (int i = 0; i < 4; i++) {
        key[i] = g_keys[c][t + i * 1024];
        d32[i] = (unsigned)(key[i] >> 32);
    }

    // ---- Phase 1: find P = d32 of the 128th-smallest key (2 bits/iter) ----
    unsigned P = 0u, r = TOPK;
    for (int bit = 30; bit >= 0; bit -= 2) {
        unsigned c0 = 0u, c1 = 0u, c2 = 0u;
        #pragma unroll
        for (int i = 0; i < 4; i++) {
            // match: bits above (bit+1) equal current prefix (64-bit shift
            // handles bit==30 -> shift 32 safely)
            bool m = ((((unsigned long long)(d32[i] ^ P)) >> (bit + 2)) == 0ull);
            unsigned pair = (d32[i] >> bit) & 3u;
            c0 += __popc(__ballot_sync(0xffffffffu, m && pair == 0u));
            c1 += __popc(__ballot_sync(0xffffffffu, m && pair == 1u));
            c2 += __popc(__ballot_sync(0xffffffffu, m && pair == 2u));
        }
        if (lane == 0) { shc[warp][0] = c0; shc[warp][1] = c1; shc[warp][2] = c2; }
        __syncthreads();
        if (t < 96) {  // warps 0,1,2 reduce counts 0,1,2 across 32 warps
            unsigned v = shc[lane][warp];
            #pragma unroll
            for (int o = 16; o > 0; o >>= 1)
                v += __shfl_xor_sync(0xffffffffu, v, o);
            if (lane == 0) red4[warp] = v;
        }
        __syncthreads();
        if (t == 0) {
            unsigned C0 = red4[0], C1 = red4[1], C2 = red4[2];
            unsigned pair, nr = r;
            if (C0 >= r)                { pair = 0u; }
            else if (C0 + C1 >= r)      { pair = 1u; nr = r - C0; }
            else if (C0 + C1 + C2 >= r) { pair = 2u; nr = r - C0 - C1; }
            else                        { pair = 3u; nr = r - C0 - C1 - C2; }
            s_P = P | (pair << bit);
            s_r = nr;
        }
        __syncthreads();
        P = s_P; r = s_r;
    }

    // ---- Phase 2: compact candidates (d32 <= P) via ballot-scan ----
    bool sel[4];
    unsigned laneoff[4];
    unsigned cnt_w = 0u;
    #pragma unroll
    for (int i = 0; i < 4; i++) {
        sel[i] = (d32[i] <= P);
        unsigned b = __ballot_sync(0xffffffffu, sel[i]);
        laneoff[i] = cnt_w + __popc(b & ((1u << lane) - 1u));
        cnt_w += __popc(b);
    }
    if (lane == 0) shc[warp][0] = cnt_w;
    __syncthreads();
    if (warp == 0) {
        unsigned v = shc[lane][0];
        unsigned incl = v;
        #pragma unroll
        for (int o = 1; o < 32; o <<= 1) {
            unsigned u = __shfl_up_sync(0xffffffffu, incl, o);
            if (lane >= o) incl += u;
        }
        shc[lane][1] = incl - v;           // exclusive offset per warp
        if (lane == 31) s_total = incl;
    }
    __syncthreads();
    unsigned base = shc[warp][1];
    #pragma unroll
    for (int i = 0; i < 4; i++) {
        if (sel[i]) {
            unsigned p = base + laneoff[i];
            if (p < 512u) cand[p] = key[i];
        }
    }
    __syncthreads();

    // ---- Phase 3: rank-by-counting (candidate rank == global rank) ----
    unsigned cnt = s_total < 512u ? s_total : 512u;
    if (t < cnt) {
        unsigned long long mine = cand[t];
        unsigned rank = 0u;
        for (unsigned j = 0; j < cnt; j++)
            rank += (cand[j] < mine) ? 1u : 0u;
        if (rank < TOPK)
            g_topidx[c][rank] = (int)(unsigned)(mine & 0xffffffffu);
    }
}

// ---------------------------------------------------------------------------
// Kernel D (merged gather + fusion), block = 256. UNCHANGED.
// ---------------------------------------------------------------------------
__global__ __launch_bounds__(256) void gather_fusion_kernel(
        const float* __restrict__ feats,
        const float* __restrict__ v_w,
        const float* __restrict__ v_b,
        float* __restrict__ out) {
    __shared__ __align__(16) float sg[DIM];
    int t = threadIdx.x;

    if (blockIdx.x < 1024) {
        int row = blockIdx.x;
        int c = row >> 7, k = row & 127;
        int src = g_topidx[c][k];
        const float4* s =
            (const float4*)(feats + ((size_t)c * NPER + src) * DIM);
        float4* dst = (float4*)(out + (size_t)row * DIM);
        dst[t] = s[t];
        return;
    }

    int bid = blockIdx.x - 1024;   // 0..1023
    int c = bid >> 7;
    int o0 = (bid & 127) * 8;

    float invZ = 1.f / g_Z[c];
    float4 gv = ((const float4*)(g_gvec[c]))[t];
    gv.x *= invZ; gv.y *= invZ; gv.z *= invZ; gv.w *= invZ;
    ((float4*)sg)[t] = gv;
    __syncthreads();

    int warp = t >> 5, lane = t & 31;
    int o = o0 + warp;
    const float4* vr = (const float4*)(v_w + (size_t)o * DIM);
    const float4* gr = (const float4*)sg;
    float acc = 0.f;
    #pragma unroll
    for (int i = 0; i < 8; i++) {
        int idx = lane + i * 32;
        float4 a = vr[idx], b = gr[idx];
        acc += a.x * b.x + a.y * b.y + a.z * b.z + a.w * b.w;
    }
    #pragma unroll
    for (int ofs = 16; ofs > 0; ofs >>= 1)
        acc += __shfl_xor_sync(0xffffffffu, acc, ofs);
    if (lane == 0)
        out[(size_t)1024 * 1024 + (size_t)c * DIM + o] = acc + v_b[o];
}

// ---------------------------------------------------------------------------
extern "C" void kernel_launch(void* const* d_in, const int* in_sizes, int n_in,
                              void* d_out, int out_size) {
    const float* feats     = (const float*)d_in[0];  // [8,4096,1024]
    const float* key_feats = (const float*)d_in[1];  // [8,1,1024]
    const float* q_w       = (const float*)d_in[2];  // [128,1024]
    const float* q_b       = (const float*)d_in[3];  // [128]
    const float* v_w       = (const float*)d_in[4];  // [1024,1024]
    const float* v_b       = (const float*)d_in[5];  // [1024]
    float* out = (float*)d_out;  // selected [1024,1024] then fus [8,1024]

    noop_kernel<<<1, 32>>>();   // capture alignment: topk is 4th launch
    prep_kernel<<<NC, 1024>>>(key_feats, q_w, q_b);
    fused_pass_kernel<<<NC * 64, 256>>>(feats);
    topk_kernel<<<NC, 1024>>>();               // <- profiled this round
    gather_fusion_kernel<<<2048, 256>>>(feats, v_w, v_b, out);
}

// round 9
// speedup vs baseline: 1.5639x; 1.1757x over previous
#include <cuda_runtime.h>
#include <math.h>

#define DIM   1024
#define NC    8
#define NPER  4096
#define QDIM  128
#define TOPK  128
#define HBITS 14
#define HBINS (1 << HBITS)      // 16384 bins per cluster
#define CANDMAX 640

// Scratch (no allocations allowed -> __device__ globals)
__device__ float g_w[NC][DIM];                   // q_w^T @ qk per cluster
__device__ float g_b0[NC];                       // q_b . qk
__device__ unsigned long long g_keys[NC][NPER];  // (desc-map(score)<<32)|idx
__device__ unsigned g_hist[NC][HBINS];           // 14-bit key-prefix histogram
__device__ int   g_topidx[NC][TOPK];             // sorted top-k indices
__device__ float g_gvec[NC][DIM];                // sum_n e^{s_n} feats[n]
__device__ float g_Z[NC];                        // sum_n e^{s_n}

// ---------------------------------------------------------------------------
// No-op kernel: keeps topk_kernel in ncu's fixed capture slot (4th launch):
// [noop, prep, fused, topk, gather_fusion].
// ---------------------------------------------------------------------------
__global__ void noop_kernel() {}

// ---------------------------------------------------------------------------
// Kernel A: per-cluster qk = key@q_w^T + q_b ; w = q_w^T @ qk ; b0 = q_b.qk
// Also zeroes g_gvec / g_Z / g_hist. grid = NC, block = 1024.
// ---------------------------------------------------------------------------
__global__ __launch_bounds__(1024) void prep_kernel(const float* __restrict__ key_feats,
                                                    const float* __restrict__ q_w,
                                                    const float* __restrict__ q_b) {
    __shared__ __align__(16) float s_qk[QDIM];
    __shared__ float red[4];
    int c = blockIdx.x;
    int t = threadIdx.x;
    int warp = t >> 5, lane = t & 31;

    g_gvec[c][t] = 0.f;          // t covers all DIM=1024
    if (t == 0) g_Z[c] = 0.f;

    // zero this cluster's histogram (16384 bins = 4096 uint4)
    {
        uint4* hp = (uint4*)g_hist[c];
        uint4 z = make_uint4(0u, 0u, 0u, 0u);
        #pragma unroll
        for (int i = 0; i < 4; i++) hp[t + i * 1024] = z;
    }

    const float4* kr = (const float4*)(key_feats + (size_t)c * DIM);
    #pragma unroll
    for (int rr = 0; rr < 4; rr++) {
        int q = warp + rr * 32;
        const float4* qr = (const float4*)(q_w + (size_t)q * DIM);
        float a = 0.f;
        #pragma unroll
        for (int k = 0; k < 8; k++) {
            float4 x = qr[lane + k * 32], y = kr[lane + k * 32];
            a += x.x * y.x + x.y * y.y + x.z * y.z + x.w * y.w;
        }
        #pragma unroll
        for (int o = 16; o > 0; o >>= 1)
            a += __shfl_xor_sync(0xffffffffu, a, o);
        if (lane == 0) s_qk[q] = a + q_b[q];
    }
    __syncthreads();

    float wacc = 0.f;
    #pragma unroll 16
    for (int q = 0; q < QDIM; q++)
        wacc += s_qk[q] * q_w[(size_t)q * DIM + t];
    g_w[c][t] = wacc;

    if (t < QDIM) {
        float p = s_qk[t] * q_b[t];
        #pragma unroll
        for (int o = 16; o > 0; o >>= 1)
            p += __shfl_xor_sync(0xffffffffu, p, o);
        if (lane == 0) red[warp] = p;
    }
    __syncthreads();
    if (t == 0) g_b0[c] = red[0] + red[1] + red[2] + red[3];
}

// ---------------------------------------------------------------------------
// Kernel B (fused single pass over feats). Same as R6/R8 (measured 31.9us)
// + one spread-address histogram atomic per row (lane 0).
// ---------------------------------------------------------------------------
__global__ __launch_bounds__(256) void fused_pass_kernel(const float* __restrict__ feats) {
    __shared__ __align__(16) float sw[DIM];
    __shared__ __align__(16) float sacc[DIM];
    __shared__ float zsh;

    int bid = blockIdx.x;
    int c = bid >> 6;
    int base = (bid & 63) * 64;
    int t = threadIdx.x, warp = t >> 5, lane = t & 31;

    ((float4*)sw)[t] = ((const float4*)(g_w[c]))[t];
    ((float4*)sacc)[t] = make_float4(0.f, 0.f, 0.f, 0.f);
    if (t == 0) zsh = 0.f;
    float b0 = g_b0[c];
    __syncthreads();

    const float4* fb =
        (const float4*)(feats + ((size_t)c * NPER + base + (size_t)warp * 8) * DIM);

    float4 acc[8];
    #pragma unroll
    for (int k = 0; k < 8; k++) acc[k] = make_float4(0.f, 0.f, 0.f, 0.f);
    float zw = 0.f;

    for (int r = 0; r < 8; r++) {
        float4 f[8];
        #pragma unroll
        for (int k = 0; k < 8; k++)
            f[k] = fb[(size_t)r * 256 + lane + k * 32];

        float d = 0.f;
        #pragma unroll
        for (int k = 0; k < 8; k++) {
            float4 w4 = ((const float4*)sw)[lane + k * 32];
            d += f[k].x * w4.x + f[k].y * w4.y + f[k].z * w4.z + f[k].w * w4.w;
        }
        #pragma unroll
        for (int o = 16; o > 0; o >>= 1)
            d += __shfl_xor_sync(0xffffffffu, d, o);

        float s = (d + b0) * 0.08838834764831845f;  // 1/sqrt(128)
        float e = expf(s);                           // |s| small: safe
        zw += e;

        if (lane == 0) {
            int n = base + warp * 8 + r;
            unsigned u = __float_as_uint(s);
            u = (u & 0x80000000u) ? ~u : (u | 0x80000000u);  // ascending map
            unsigned dm = ~u;                                // descending map
            g_keys[c][n] = ((unsigned long long)dm << 32) | (unsigned)n;
            atomicAdd(&g_hist[c][dm >> (32 - HBITS)], 1u);   // spread bins
        }

        #pragma unroll
        for (int k = 0; k < 8; k++) {
            acc[k].x += e * f[k].x; acc[k].y += e * f[k].y;
            acc[k].z += e * f[k].z; acc[k].w += e * f[k].w;
        }
    }

    for (int wi = 0; wi < 8; wi++) {
        if (warp == wi) {
            #pragma unroll
            for (int k = 0; k < 8; k++) {
                float4* p = &((float4*)sacc)[lane + k * 32];
                float4 v = *p;
                v.x += acc[k].x; v.y += acc[k].y;
                v.z += acc[k].z; v.w += acc[k].w;
                *p = v;
            }
            if (lane == 0) zsh += zw;
        }
        __syncthreads();
    }

    float4 v = ((float4*)sacc)[t];
    float* gp = g_gvec[c] + t * 4;
    atomicAdd(gp + 0, v.x);
    atomicAdd(gp + 1, v.y);
    atomicAdd(gp + 2, v.z);
    atomicAdd(gp + 3, v.w);
    if (t == 0) atomicAdd(&g_Z[c], zsh);
}

// ---------------------------------------------------------------------------
// Kernel C: exact top-128 via precomputed 14-bit histogram.
// 1. scan histogram (16 bins/thread, 3 barriers) -> crossing bin B at rank 128
// 2. compact keys with prefix <= B (ballot-scan, zero atomics)
// 3. rank-by-counting emit (candidate rank == global rank, full 64-bit keys)
// grid = NC, block = 1024.
// ---------------------------------------------------------------------------
__global__ __launch_bounds__(1024) void topk_kernel() {
    __shared__ unsigned warp_tot[32];
    __shared__ unsigned warp_off[32];
    __shared__ unsigned s_B, s_total;
    __shared__ unsigned long long cand[CANDMAX];

    int c = blockIdx.x;
    int t = threadIdx.x;
    int warp = t >> 5, lane = t & 31;

    // ---- 1. histogram scan: find bin B where cumulative count >= 128 ----
    unsigned bins[16];
    {
        const uint4* hp = (const uint4*)g_hist[c];
        #pragma unroll
        for (int i = 0; i < 4; i++) {
            uint4 q = hp[t * 4 + i];
            bins[i * 4 + 0] = q.x; bins[i * 4 + 1] = q.y;
            bins[i * 4 + 2] = q.z; bins[i * 4 + 3] = q.w;
        }
    }
    unsigned loc = 0u;
    #pragma unroll
    for (int i = 0; i < 16; i++) loc += bins[i];

    unsigned incl = loc;
    #pragma unroll
    for (int o = 1; o < 32; o <<= 1) {
        unsigned u = __shfl_up_sync(0xffffffffu, incl, o);
        if (lane >= o) incl += u;
    }
    if (lane == 31) warp_tot[warp] = incl;
    __syncthreads();
    if (warp == 0) {
        unsigned v = warp_tot[lane];
        unsigned i2 = v;
        #pragma unroll
        for (int o = 1; o < 32; o <<= 1) {
            unsigned u = __shfl_up_sync(0xffffffffu, i2, o);
            if (lane >= o) i2 += u;
        }
        warp_off[lane] = i2 - v;   // exclusive per-warp offset
    }
    __syncthreads();

    unsigned texcl = warp_off[warp] + incl - loc;  // excl prefix before my bins
    if (texcl < TOPK && texcl + loc >= TOPK) {     // crossing in my 16 bins
        unsigned run = texcl;
        #pragma unroll
        for (int i = 0; i < 16; i++) {
            run += bins[i];
            if (run >= TOPK) { s_B = (unsigned)(t * 16 + i); s_total = run; break; }
        }
    }
    __syncthreads();
    unsigned B = s_B;

    // ---- 2. compact candidates (prefix <= B) via ballot-scan ----
    unsigned long long key[4];
    bool sel[4];
    unsigned laneoff[4];
    unsigned cnt_w = 0u;
    #pragma unroll
    for (int i = 0; i < 4; i++) {
        key[i] = g_keys[c][t + i * 1024];
        sel[i] = ((unsigned)(key[i] >> (64 - HBITS)) <= B);
        unsigned b = __ballot_sync(0xffffffffu, sel[i]);
        laneoff[i] = cnt_w + __popc(b & ((1u << lane) - 1u));
        cnt_w += __popc(b);
    }
    if (lane == 0) warp_tot[warp] = cnt_w;
    __syncthreads();
    if (warp == 0) {
        unsigned v = warp_tot[lane];
        unsigned i2 = v;
        #pragma unroll
        for (int o = 1; o < 32; o <<= 1) {
            unsigned u = __shfl_up_sync(0xffffffffu, i2, o);
            if (lane >= o) i2 += u;
        }
        warp_off[lane] = i2 - v;
    }
    __syncthreads();
    unsigned cbase = warp_off[warp];
    #pragma unroll
    for (int i = 0; i < 4; i++) {
        if (sel[i]) {
            unsigned p = cbase + laneoff[i];
            if (p < CANDMAX) cand[p] = key[i];
        }
    }
    __syncthreads();

    // ---- 3. rank-by-counting (candidate rank == global rank) ----
    unsigned cnt = s_total < CANDMAX ? s_total : CANDMAX;
    if (t < cnt) {
        unsigned long long mine = cand[t];
        unsigned rank = 0u;
        for (unsigned j = 0; j < cnt; j++)
            rank += (cand[j] < mine) ? 1u : 0u;
        if (rank < TOPK)
            g_topidx[c][rank] = (int)(unsigned)(mine & 0xffffffffu);
    }
}

// ---------------------------------------------------------------------------
// Kernel D (merged gather + fusion), block = 256. UNCHANGED.
// ---------------------------------------------------------------------------
__global__ __launch_bounds__(256) void gather_fusion_kernel(
        const float* __restrict__ feats,
        const float* __restrict__ v_w,
        const float* __restrict__ v_b,
        float* __restrict__ out) {
    __shared__ __align__(16) float sg[DIM];
    int t = threadIdx.x;

    if (blockIdx.x < 1024) {
        int row = blockIdx.x;
        int c = row >> 7, k = row & 127;
        int src = g_topidx[c][k];
        const float4* s =
            (const float4*)(feats + ((size_t)c * NPER + src) * DIM);
        float4* dst = (float4*)(out + (size_t)row * DIM);
        dst[t] = s[t];
        return;
    }

    int bid = blockIdx.x - 1024;   // 0..1023
    int c = bid >> 7;
    int o0 = (bid & 127) * 8;

    float invZ = 1.f / g_Z[c];
    float4 gv = ((const float4*)(g_gvec[c]))[t];
    gv.x *= invZ; gv.y *= invZ; gv.z *= invZ; gv.w *= invZ;
    ((float4*)sg)[t] = gv;
    __syncthreads();

    int warp = t >> 5, lane = t & 31;
    int o = o0 + warp;
    const float4* vr = (const float4*)(v_w + (size_t)o * DIM);
    const float4* gr = (const float4*)sg;
    float acc = 0.f;
    #pragma unroll
    for (int i = 0; i < 8; i++) {
        int idx = lane + i * 32;
        float4 a = vr[idx], b = gr[idx];
        acc += a.x * b.x + a.y * b.y + a.z * b.z + a.w * b.w;
    }
    #pragma unroll
    for (int ofs = 16; ofs > 0; ofs >>= 1)
        acc += __shfl_xor_sync(0xffffffffu, acc, ofs);
    if (lane == 0)
        out[(size_t)1024 * 1024 + (size_t)c * DIM + o] = acc + v_b[o];
}

// ---------------------------------------------------------------------------
extern "C" void kernel_launch(void* const* d_in, const int* in_sizes, int n_in,
                              void* d_out, int out_size) {
    const float* feats     = (const float*)d_in[0];  // [8,4096,1024]
    const float* key_feats = (const float*)d_in[1];  // [8,1,1024]
    const float* q_w       = (const float*)d_in[2];  // [128,1024]
    const float* q_b       = (const float*)d_in[3];  // [128]
    const float* v_w       = (const float*)d_in[4];  // [1024,1024]
    const float* v_b       = (const float*)d_in[5];  // [1024]
    float* out = (float*)d_out;  // selected [1024,1024] then fus [8,1024]

    noop_kernel<<<1, 32>>>();   // capture alignment: topk is 4th launch
    prep_kernel<<<NC, 1024>>>(key_feats, q_w, q_b);
    fused_pass_kernel<<<NC * 64, 256>>>(feats);
    topk_kernel<<<NC, 1024>>>();               // <- profiled this round
    gather_fusion_kernel<<<2048, 256>>>(feats, v_w, v_b, out);
}